// round 9
// baseline (speedup 1.0000x reference)
#include <cuda_runtime.h>
#include <cstdint>

#define S_LEN 2048
#define B_SZ  32
#define I_DIM 256
#define H_DIM 512

#define NCLUSTERS    16
#define CRANKS       8
#define ROWS_PER_CTA 64
#define REC_THREADS  512

// ---------------- PTX helpers ----------------
__device__ __forceinline__ uint32_t smem_u32(const void* p) {
    uint32_t a;
    asm("{ .reg .u64 t; cvta.to.shared.u64 t, %1; cvt.u32.u64 %0, t; }" : "=r"(a) : "l"(p));
    return a;
}
__device__ __forceinline__ uint32_t mapa_cluster(uint32_t addr, uint32_t rank) {
    uint32_t r;
    asm("mapa.shared::cluster.u32 %0, %1, %2;" : "=r"(r) : "r"(addr), "r"(rank));
    return r;
}
__device__ __forceinline__ void mbar_init(uint32_t mbar, uint32_t cnt) {
    asm volatile("mbarrier.init.shared.b64 [%0], %1;" :: "r"(mbar), "r"(cnt) : "memory");
}
__device__ __forceinline__ void mbar_wait(uint32_t mbar, uint32_t phase) {
    uint32_t done = 0;
    while (!done) {
        asm volatile(
            "{\n\t.reg .pred p;\n\t"
            "mbarrier.try_wait.parity.acquire.cluster.shared::cta.b64 p, [%1], %2, 0x989680;\n\t"
            "selp.b32 %0, 1, 0, p;\n\t}"
            : "=r"(done) : "r"(mbar), "r"(phase) : "memory");
    }
}
// release-arrive on a peer CTA's mbarrier (cluster scope)
__device__ __forceinline__ void mbar_arrive_cluster(uint32_t remote_mbar) {
    asm volatile("mbarrier.arrive.release.cluster.shared::cluster.b64 _, [%0];"
                 :: "r"(remote_mbar) : "memory");
}
// 16-byte load from cluster shared window (remote or local CTA)
__device__ __forceinline__ void lds_v2b64_cluster(uint32_t addr,
                                                  unsigned long long& lo,
                                                  unsigned long long& hi) {
    asm volatile("ld.shared::cluster.v2.b64 {%0, %1}, [%2];"
                 : "=l"(lo), "=l"(hi) : "r"(addr));
}
__device__ __forceinline__ unsigned long long ffma2(unsigned long long a, unsigned long long b,
                                                    unsigned long long c) {
    unsigned long long d;
    asm("fma.rn.f32x2 %0, %1, %2, %3;" : "=l"(d) : "l"(a), "l"(b), "l"(c));
    return d;
}
__device__ __forceinline__ float fold2(unsigned long long v) {
    union { unsigned long long u; float2 f; } c; c.u = v;
    return c.f.x + c.f.y;
}
__device__ __forceinline__ float fast_tanh(float h) {
    float hc = fminf(fmaxf(h, -15.f), 15.f);
    float e2 = __expf(2.f * hc);
    return __fdividef(e2 - 1.f, e2 + 1.f);
}
__device__ __forceinline__ void cluster_sync() {
    asm volatile("barrier.cluster.arrive.aligned;\n\tbarrier.cluster.wait.aligned;" ::: "memory");
}

// ---------------- xproj GEMM (R3-proven): out[m,n] = sum_k x[m,k] * Wx[n,k] ----------------
#define BM 128
#define BN 128
#define BK 16

__global__ void __launch_bounds__(256, 2)
xproj_kernel(const float* __restrict__ x,
             const float* __restrict__ Wx,
             float* __restrict__ out)
{
    __shared__ float As[BK][BM];
    __shared__ float Bs[BK][BN];
    const int tid = threadIdx.x;
    const int m0 = blockIdx.y * BM;
    const int n0 = blockIdx.x * BN;
    const int tx = tid & 15;
    const int ty = tid >> 4;

    float acc[8][8];
#pragma unroll
    for (int i = 0; i < 8; i++)
#pragma unroll
        for (int j = 0; j < 8; j++) acc[i][j] = 0.f;

    const float* Aptr = x  + (size_t)m0 * I_DIM;
    const float* Bptr = Wx + (size_t)n0 * I_DIM;

    for (int k0 = 0; k0 < I_DIM; k0 += BK) {
#pragma unroll
        for (int l = 0; l < 2; l++) {
            int idx = tid + l * 256;
            int r   = idx >> 2;
            int c4  = (idx & 3) * 4;
            float4 a = *(const float4*)(Aptr + (size_t)r * I_DIM + k0 + c4);
            As[c4 + 0][r] = a.x; As[c4 + 1][r] = a.y;
            As[c4 + 2][r] = a.z; As[c4 + 3][r] = a.w;
            float4 b = *(const float4*)(Bptr + (size_t)r * I_DIM + k0 + c4);
            Bs[c4 + 0][r] = b.x; Bs[c4 + 1][r] = b.y;
            Bs[c4 + 2][r] = b.z; Bs[c4 + 3][r] = b.w;
        }
        __syncthreads();
#pragma unroll
        for (int kk = 0; kk < BK; kk++) {
            float ra[8], rb[8];
            float4 ra0 = *(const float4*)&As[kk][ty * 8];
            float4 ra1 = *(const float4*)&As[kk][ty * 8 + 4];
            ra[0]=ra0.x; ra[1]=ra0.y; ra[2]=ra0.z; ra[3]=ra0.w;
            ra[4]=ra1.x; ra[5]=ra1.y; ra[6]=ra1.z; ra[7]=ra1.w;
            float4 rb0 = *(const float4*)&Bs[kk][tx * 8];
            float4 rb1 = *(const float4*)&Bs[kk][tx * 8 + 4];
            rb[0]=rb0.x; rb[1]=rb0.y; rb[2]=rb0.z; rb[3]=rb0.w;
            rb[4]=rb1.x; rb[5]=rb1.y; rb[6]=rb1.z; rb[7]=rb1.w;
#pragma unroll
            for (int i = 0; i < 8; i++)
#pragma unroll
                for (int j = 0; j < 8; j++)
                    acc[i][j] += ra[i] * rb[j];
        }
        __syncthreads();
    }

#pragma unroll
    for (int i = 0; i < 8; i++) {
        float* o = out + (size_t)(m0 + ty * 8 + i) * H_DIM + n0 + tx * 8;
        *(float4*)o       = make_float4(acc[i][0], acc[i][1], acc[i][2], acc[i][3]);
        *(float4*)(o + 4) = make_float4(acc[i][4], acc[i][5], acc[i][6], acc[i][7]);
    }
}

// ---------------- recurrence (PULL model) ----------------
// 16 clusters x 8 CTAs; cluster c: batches (2c, 2c+1). CTA rank r owns rows
// [r*64, r*64+64), Wh slice in registers (f32x2 pairs). th lives ONLY in the
// owner's smem: th[parity][batch][64]. Peers read it via ld.shared::cluster
// during the GEMV (warp kb's k-chunk [32kb,+32) lives wholly in CTA kb>>1).
// Signaling: 16 mbarriers [parity][src], count=1. Source CTA's threads t<8
// release-arrive at each peer's mbar[parity][src_rank] after its tail writes
// th + bar.sync. Dest warp waits only on its own source's mbar -> per-source
// fine-grained start, no sends, no ingress accounting.
struct RecSmem {
    float th[2][2][ROWS_PER_CTA];  // [parity][batch][row]  1KB, own rows only
    float part[16][128];           // partials, column = owner tid
    unsigned long long mbar[2][CRANKS];  // [parity][src]
};

__global__ void __cluster_dims__(CRANKS, 1, 1) __launch_bounds__(REC_THREADS, 1)
rec_kernel(const float* __restrict__ Wh,
           const float* __restrict__ tau,
           const float* __restrict__ bias,
           float* __restrict__ out)
{
    __shared__ __align__(16) RecSmem sm;

    const int cid  = blockIdx.x / CRANKS;
    const int rank = blockIdx.x % CRANKS;
    const int t    = threadIdx.x;
    const int jp   = t & 31;
    const int kb   = t >> 5;
    const int j0   = 2 * jp;
    const int src  = kb >> 1;                 // cluster CTA owning this warp's k-chunk
    const uint32_t ck = (uint32_t)(kb & 1) * 128u;  // byte offset of chunk within source rows

    // Wh slice in registers (rows j0, j0+1; k in [kb*32, kb*32+32))
    unsigned long long wp0[16], wp1[16];
    {
        const ulonglong2* r0 = (const ulonglong2*)(Wh + (size_t)(rank * ROWS_PER_CTA + j0)     * H_DIM + kb * 32);
        const ulonglong2* r1 = (const ulonglong2*)(Wh + (size_t)(rank * ROWS_PER_CTA + j0 + 1) * H_DIM + kb * 32);
#pragma unroll
        for (int i = 0; i < 8; i++) {
            ulonglong2 a = r0[i]; wp0[2*i] = a.x; wp0[2*i+1] = a.y;
            ulonglong2 b = r1[i]; wp1[2*i] = b.x; wp1[2*i+1] = b.y;
        }
    }

    const uint32_t th_base   = smem_u32(&sm.th[0][0][0]);
    const uint32_t mbar_base = smem_u32(&sm.mbar[0][0]);

    // cluster-window addresses
    uint32_t peer_th[CRANKS], peer_mbar[CRANKS];
#pragma unroll
    for (int r = 0; r < CRANKS; r++) {
        peer_th[r]   = mapa_cluster(th_base, r);
        peer_mbar[r] = mapa_cluster(mbar_base, r);
    }
    // this warp's source-data addresses (batch 0 / batch 1), + parity*512 later
    const uint32_t srcA = peer_th[src] + ck;          // [P][0][chunk]
    const uint32_t srcB = srcA + 256u;                // [P][1][chunk]
    // this warp's wait mbar: mbar[P][src] -> mbar_base + (P*8+src)*8
    const uint32_t wait_m = mbar_base + (uint32_t)src * 8u;

    if (t == 0) {
#pragma unroll
        for (int m = 0; m < 2 * CRANKS; m++)
            mbar_init(mbar_base + m * 8, 1);
    }
    __syncthreads();
    cluster_sync();   // all peers' mbars live before any arrive

    // tail state (t < 128): one (batch, row) output per thread
    const int bb = t >> 6;
    const int j  = t & 63;
    const int hg = rank * ROWS_PER_CTA + j;
    const int b  = cid * 2 + bb;
    float* outp = out + (size_t)b * S_LEN * H_DIM + hg;

    float h = 0.f, inv_tau = 1.f, Acoef = 0.f, c0 = 0.f, pre = 0.f;
    if (t < 128) {
        inv_tau = 1.0f / tau[hg];
        Acoef   = 1.0f - inv_tau;
        c0      = bias[hg] * inv_tau;
    }
    // arrive address for thread t<8: peer t's mbar[P^1][my rank]
    const uint32_t arr_base = (t < 8) ? (peer_mbar[t & 7] + (uint32_t)rank * 8u) : 0u;

    // ---- step 0: v = 0, h = xp/tau + bias/tau ----
    if (t < 128) {
        float xp = outp[0];
        pre = fmaf(xp, inv_tau, c0);
        h = pre;
        sm.th[1][bb][j] = fast_tanh(h);
        asm volatile("bar.sync 1, 128;" ::: "memory");
        if (t < 8) mbar_arrive_cluster(arr_base + 8u * CRANKS);   // parity 1
        outp[0] = h;
        float xn = outp[(size_t)1 * H_DIM];
        pre = fmaf(xn, inv_tau, c0);
    }

    uint32_t ph0 = 0, ph1 = 0;

#define STEP_BODY(STEP, P, PH, LAST)                                               \
    {                                                                              \
        float xn = 0.f;                                                            \
        if (t < 128 && !(LAST)) xn = outp[(size_t)((STEP) + 1) * H_DIM];           \
        mbar_wait(wait_m + (P) * (8u * CRANKS), (PH));                             \
        unsigned long long a00 = 0ull, a01 = 0ull, a10 = 0ull, a11 = 0ull;         \
        const uint32_t _sa = srcA + (P) * 512u;                                    \
        const uint32_t _sb = srcB + (P) * 512u;                                    \
        _Pragma("unroll")                                                          \
        for (int i = 0; i < 8; i++) {                                              \
            unsigned long long ux, uy, vx, vy;                                     \
            lds_v2b64_cluster(_sa + i * 16u, ux, uy);                              \
            lds_v2b64_cluster(_sb + i * 16u, vx, vy);                              \
            a00 = ffma2(wp0[2*i],   ux, a00);                                      \
            a00 = ffma2(wp0[2*i+1], uy, a00);                                      \
            a01 = ffma2(wp1[2*i],   ux, a01);                                      \
            a01 = ffma2(wp1[2*i+1], uy, a01);                                      \
            a10 = ffma2(wp0[2*i],   vx, a10);                                      \
            a10 = ffma2(wp0[2*i+1], vy, a10);                                      \
            a11 = ffma2(wp1[2*i],   vx, a11);                                      \
            a11 = ffma2(wp1[2*i+1], vy, a11);                                      \
        }                                                                          \
        *(float2*)&sm.part[kb][j0]      = make_float2(fold2(a00), fold2(a01));     \
        *(float2*)&sm.part[kb][64 + j0] = make_float2(fold2(a10), fold2(a11));     \
        __syncthreads();                                                           \
        if (t < 128) {                                                             \
            float v0 = sm.part[0][t], v1 = sm.part[1][t];                          \
            float v2 = sm.part[2][t], v3 = sm.part[3][t];                          \
            _Pragma("unroll")                                                      \
            for (int w = 4; w < 16; w += 4) {                                      \
                v0 += sm.part[w][t];     v1 += sm.part[w + 1][t];                  \
                v2 += sm.part[w + 2][t]; v3 += sm.part[w + 3][t];                  \
            }                                                                      \
            float v = (v0 + v1) + (v2 + v3);                                       \
            h = fmaf(h, Acoef, fmaf(v, inv_tau, pre));                             \
            if (!(LAST)) {                                                         \
                sm.th[(P) ^ 1][bb][j] = fast_tanh(h);                              \
                asm volatile("bar.sync 1, 128;" ::: "memory");                     \
                if (t < 8)                                                         \
                    mbar_arrive_cluster(arr_base + ((P) ^ 1) * (8u * CRANKS));     \
            }                                                                      \
            outp[(size_t)(STEP) * H_DIM] = h;                                      \
            pre = fmaf(xn, inv_tau, c0);                                           \
        }                                                                          \
        (PH) ^= 1;                                                                 \
    }

    for (int s = 1; s < S_LEN - 1; s += 2) {
        STEP_BODY(s,     1, ph1, 0)
        STEP_BODY(s + 1, 0, ph0, 0)
    }
    STEP_BODY(S_LEN - 1, 1, ph1, 1)
#undef STEP_BODY

    cluster_sync();   // keep smem alive while peers may still read it remotely
}

extern "C" void kernel_launch(void* const* d_in, const int* in_sizes, int n_in,
                              void* d_out, int out_size)
{
    const float* x    = (const float*)d_in[0];
    const float* Wx   = (const float*)d_in[1];
    const float* Wh   = (const float*)d_in[2];
    const float* tau  = (const float*)d_in[3];
    const float* bias = (const float*)d_in[4];
    float* out = (float*)d_out;

    dim3 g1(H_DIM / BN, (B_SZ * S_LEN) / BM);
    xproj_kernel<<<g1, 256>>>(x, Wx, out);

    rec_kernel<<<NCLUSTERS * CRANKS, REC_THREADS>>>(Wh, tau, bias, out);
}

// round 10
// speedup vs baseline: 1.4776x; 1.4776x over previous
#include <cuda_runtime.h>
#include <cstdint>

#define S_LEN 2048
#define B_SZ  32
#define I_DIM 256
#define H_DIM 512

#define NCLUSTERS    16
#define CRANKS       8
#define ROWS_PER_CTA 64
#define REC_THREADS  512

// ---------------- PTX helpers ----------------
__device__ __forceinline__ uint32_t smem_u32(const void* p) {
    uint32_t a;
    asm("{ .reg .u64 t; cvta.to.shared.u64 t, %1; cvt.u32.u64 %0, t; }" : "=r"(a) : "l"(p));
    return a;
}
__device__ __forceinline__ uint32_t mapa_cluster(uint32_t addr, uint32_t rank) {
    uint32_t r;
    asm("mapa.shared::cluster.u32 %0, %1, %2;" : "=r"(r) : "r"(addr), "r"(rank));
    return r;
}
__device__ __forceinline__ void mbar_init(uint32_t mbar, uint32_t cnt) {
    asm volatile("mbarrier.init.shared.b64 [%0], %1;" :: "r"(mbar), "r"(cnt) : "memory");
}
__device__ __forceinline__ void mbar_expect_tx(uint32_t mbar, uint32_t bytes) {
    asm volatile("mbarrier.arrive.expect_tx.shared.b64 _, [%0], %1;" :: "r"(mbar), "r"(bytes) : "memory");
}
__device__ __forceinline__ void mbar_wait(uint32_t mbar, uint32_t phase) {
    uint32_t done = 0;
    while (!done) {
        asm volatile(
            "{\n\t.reg .pred p;\n\t"
            "mbarrier.try_wait.parity.acquire.cluster.shared::cta.b64 p, [%1], %2, 0x989680;\n\t"
            "selp.b32 %0, 1, 0, p;\n\t}"
            : "=r"(done) : "r"(mbar), "r"(phase) : "memory");
    }
}
__device__ __forceinline__ void st_async_b64(uint32_t daddr, unsigned long long v, uint32_t mbar) {
    asm volatile("st.async.shared::cluster.mbarrier::complete_tx::bytes.b64 [%0], %1, [%2];"
                 :: "r"(daddr), "l"(v), "r"(mbar) : "memory");
}
__device__ __forceinline__ unsigned long long ffma2(unsigned long long a, unsigned long long b,
                                                    unsigned long long c) {
    unsigned long long d;
    asm("fma.rn.f32x2 %0, %1, %2, %3;" : "=l"(d) : "l"(a), "l"(b), "l"(c));
    return d;
}
__device__ __forceinline__ float fold2(unsigned long long v) {
    union { unsigned long long u; float2 f; } c; c.u = v;
    return c.f.x + c.f.y;
}
__device__ __forceinline__ unsigned long long pack2(float x, float y) {
    unsigned long long r;
    asm("mov.b64 %0, {%1, %2};" : "=l"(r) : "r"(__float_as_uint(x)), "r"(__float_as_uint(y)));
    return r;
}
__device__ __forceinline__ float fast_tanh(float h) {
    float hc = fminf(fmaxf(h, -15.f), 15.f);
    float e2 = __expf(2.f * hc);
    return __fdividef(e2 - 1.f, e2 + 1.f);
}
__device__ __forceinline__ void cluster_sync() {
    asm volatile("barrier.cluster.arrive.aligned;\n\tbarrier.cluster.wait.aligned;" ::: "memory");
}

// ---------------- xproj GEMM (R3-proven): out[m,n] = sum_k x[m,k] * Wx[n,k] ----------------
#define BM 128
#define BN 128
#define BK 16

__global__ void __launch_bounds__(256, 2)
xproj_kernel(const float* __restrict__ x,
             const float* __restrict__ Wx,
             float* __restrict__ out)
{
    __shared__ float As[BK][BM];
    __shared__ float Bs[BK][BN];
    const int tid = threadIdx.x;
    const int m0 = blockIdx.y * BM;
    const int n0 = blockIdx.x * BN;
    const int tx = tid & 15;
    const int ty = tid >> 4;

    float acc[8][8];
#pragma unroll
    for (int i = 0; i < 8; i++)
#pragma unroll
        for (int j = 0; j < 8; j++) acc[i][j] = 0.f;

    const float* Aptr = x  + (size_t)m0 * I_DIM;
    const float* Bptr = Wx + (size_t)n0 * I_DIM;

    for (int k0 = 0; k0 < I_DIM; k0 += BK) {
#pragma unroll
        for (int l = 0; l < 2; l++) {
            int idx = tid + l * 256;
            int r   = idx >> 2;
            int c4  = (idx & 3) * 4;
            float4 a = *(const float4*)(Aptr + (size_t)r * I_DIM + k0 + c4);
            As[c4 + 0][r] = a.x; As[c4 + 1][r] = a.y;
            As[c4 + 2][r] = a.z; As[c4 + 3][r] = a.w;
            float4 b = *(const float4*)(Bptr + (size_t)r * I_DIM + k0 + c4);
            Bs[c4 + 0][r] = b.x; Bs[c4 + 1][r] = b.y;
            Bs[c4 + 2][r] = b.z; Bs[c4 + 3][r] = b.w;
        }
        __syncthreads();
#pragma unroll
        for (int kk = 0; kk < BK; kk++) {
            float ra[8], rb[8];
            float4 ra0 = *(const float4*)&As[kk][ty * 8];
            float4 ra1 = *(const float4*)&As[kk][ty * 8 + 4];
            ra[0]=ra0.x; ra[1]=ra0.y; ra[2]=ra0.z; ra[3]=ra0.w;
            ra[4]=ra1.x; ra[5]=ra1.y; ra[6]=ra1.z; ra[7]=ra1.w;
            float4 rb0 = *(const float4*)&Bs[kk][tx * 8];
            float4 rb1 = *(const float4*)&Bs[kk][tx * 8 + 4];
            rb[0]=rb0.x; rb[1]=rb0.y; rb[2]=rb0.z; rb[3]=rb0.w;
            rb[4]=rb1.x; rb[5]=rb1.y; rb[6]=rb1.z; rb[7]=rb1.w;
#pragma unroll
            for (int i = 0; i < 8; i++)
#pragma unroll
                for (int j = 0; j < 8; j++)
                    acc[i][j] += ra[i] * rb[j];
        }
        __syncthreads();
    }

#pragma unroll
    for (int i = 0; i < 8; i++) {
        float* o = out + (size_t)(m0 + ty * 8 + i) * H_DIM + n0 + tx * 8;
        *(float4*)o       = make_float4(acc[i][0], acc[i][1], acc[i][2], acc[i][3]);
        *(float4*)(o + 4) = make_float4(acc[i][4], acc[i][5], acc[i][6], acc[i][7]);
    }
}

// ---------------- recurrence ----------------
// R7 data path (push, scalar b64 pairs, broadcast-LDS FFMA2 GEMV, cf partials)
// + PER-SOURCE mbarriers: mbar[parity][src], each expecting 512B (one source's
// 64 b64 messages). Warp kb waits ONLY on mbar[P][kb>>1] -> unblocks after its
// source's 64 messages drain; source streams drain concurrently; cluster skew
// no longer globally serializes. Re-arm inline after wait (lane 0, even warp).
struct RecSmem {
    float th[2][2][H_DIM];              // [buf][batch][k]  8KB (st.async dest)
    float part[16][128];                // partials, column = owner tid
    unsigned long long mbar[2][CRANKS]; // [parity][src]
};

__global__ void __cluster_dims__(CRANKS, 1, 1) __launch_bounds__(REC_THREADS, 1)
rec_kernel(const float* __restrict__ Wh,
           const float* __restrict__ tau,
           const float* __restrict__ bias,
           float* __restrict__ out)
{
    __shared__ __align__(16) RecSmem sm;

    const int cid  = blockIdx.x / CRANKS;
    const int rank = blockIdx.x % CRANKS;
    const int t    = threadIdx.x;
    const int jp   = t & 31;
    const int kb   = t >> 5;
    const int j0   = 2 * jp;
    const int src  = kb >> 1;      // cluster CTA sourcing this warp's k-chunk

    // Wh slice in registers (rows j0, j0+1; k in [kb*32, kb*32+32))
    unsigned long long wp0[16], wp1[16];
    {
        const ulonglong2* r0 = (const ulonglong2*)(Wh + (size_t)(rank * ROWS_PER_CTA + j0)     * H_DIM + kb * 32);
        const ulonglong2* r1 = (const ulonglong2*)(Wh + (size_t)(rank * ROWS_PER_CTA + j0 + 1) * H_DIM + kb * 32);
#pragma unroll
        for (int i = 0; i < 8; i++) {
            ulonglong2 a = r0[i]; wp0[2*i] = a.x; wp0[2*i+1] = a.y;
            ulonglong2 b = r1[i]; wp1[2*i] = b.x; wp1[2*i+1] = b.y;
        }
    }

    const uint32_t th_base   = smem_u32(&sm.th[0][0][0]);
    const uint32_t mbar_base = smem_u32(&sm.mbar[0][0]);
    const uint32_t mbar_rel  = mbar_base - th_base;

    uint32_t peer_th[CRANKS];
#pragma unroll
    for (int r = 0; r < CRANKS; r++) peer_th[r] = mapa_cluster(th_base, r);

    // init + arm all 16 mbars: [p][s] at offset (p*8+s)*8
    if (t < 2 * CRANKS) {
        mbar_init(mbar_base + t * 8, 1);
        mbar_expect_tx(mbar_base + t * 8, 512);
    }
    __syncthreads();
    cluster_sync();   // peers' mbars live before any st.async

    // this warp's wait mbar for parity P: mbar_base + (P*8 + src)*8
    const uint32_t wait_m = mbar_base + (uint32_t)src * 8u;
    const bool rearm = (jp == 0) && ((kb & 1) == 0);   // one lane per source mbar

    // tail state (t < 128): one (batch, row) output per thread
    const int bb = t >> 6;
    const int j  = t & 63;
    const int hg = rank * ROWS_PER_CTA + j;
    const int b  = cid * 2 + bb;
    float* outp = out + (size_t)b * S_LEN * H_DIM + hg;

    float h = 0.f, inv_tau = 1.f, Acoef = 0.f, c0 = 0.f, pre = 0.f;
    if (t < 128) {
        inv_tau = 1.0f / tau[hg];
        Acoef   = 1.0f - inv_tau;
        c0      = bias[hg] * inv_tau;
    }
    // b64 destination offset: even-row base of this thread's pair
    const uint32_t send_off = (uint32_t)(bb * H_DIM + (hg & ~1)) * 4u;
    const int peer0 = (t & 1) * 4;   // even lane: peers 0-3, odd: peers 4-7
    // sender's target mbar offset within peer block: (P^1)*64 + rank*8
    const uint32_t msend_base = mbar_rel + (uint32_t)rank * 8u;

    // ---- step 0: v = 0, h = xp/tau + bias/tau ----
    if (t < 128) {
        float xp = outp[0];
        pre = fmaf(xp, inv_tau, c0);
        h = pre;
        float thv = fast_tanh(h);
        float tho = __shfl_xor_sync(0xffffffffu, thv, 1);
        float ho  = __shfl_xor_sync(0xffffffffu, h,   1);
        if (!(t & 1)) *(float2*)outp = make_float2(h, ho);
        unsigned long long pk = (t & 1) ? pack2(tho, thv) : pack2(thv, tho);
        uint32_t d = (uint32_t)(2 * H_DIM * 4) + send_off;   // parity-1 buffer
        uint32_t m = msend_base + 64u;                       // mbar[1][rank]
#pragma unroll
        for (int rr = 0; rr < 4; rr++)
            st_async_b64(peer_th[peer0 + rr] + d, pk, peer_th[peer0 + rr] + m);
        float xn = outp[(size_t)1 * H_DIM];                  // prefetch step 1
        pre = fmaf(xn, inv_tau, c0);
    }

    uint32_t ph0 = 0, ph1 = 0;

#define STEP_BODY(STEP, P, PH, LAST)                                               \
    {                                                                              \
        float xn = 0.f;                                                            \
        if (t < 128 && !(LAST)) xn = outp[(size_t)((STEP) + 1) * H_DIM];           \
        mbar_wait(wait_m + (P) * 64u, (PH));                                       \
        if (rearm) mbar_expect_tx(wait_m + (P) * 64u, 512);                        \
        const ulonglong2* t0 = (const ulonglong2*)&sm.th[(P)][0][kb * 32];         \
        const ulonglong2* t1 = (const ulonglong2*)&sm.th[(P)][1][kb * 32];         \
        unsigned long long a00 = 0ull, a01 = 0ull, a10 = 0ull, a11 = 0ull;         \
        _Pragma("unroll")                                                          \
        for (int i = 0; i < 8; i++) {                                              \
            ulonglong2 U = t0[i];                                                  \
            ulonglong2 V = t1[i];                                                  \
            a00 = ffma2(wp0[2*i],   U.x, a00);                                     \
            a00 = ffma2(wp0[2*i+1], U.y, a00);                                     \
            a01 = ffma2(wp1[2*i],   U.x, a01);                                     \
            a01 = ffma2(wp1[2*i+1], U.y, a01);                                     \
            a10 = ffma2(wp0[2*i],   V.x, a10);                                     \
            a10 = ffma2(wp0[2*i+1], V.y, a10);                                     \
            a11 = ffma2(wp1[2*i],   V.x, a11);                                     \
            a11 = ffma2(wp1[2*i+1], V.y, a11);                                     \
        }                                                                          \
        *(float2*)&sm.part[kb][j0]      = make_float2(fold2(a00), fold2(a01));     \
        *(float2*)&sm.part[kb][64 + j0] = make_float2(fold2(a10), fold2(a11));     \
        __syncthreads();                                                           \
        if (t < 128) {                                                             \
            float v0 = sm.part[0][t], v1 = sm.part[1][t];                          \
            float v2 = sm.part[2][t], v3 = sm.part[3][t];                          \
            _Pragma("unroll")                                                      \
            for (int w = 4; w < 16; w += 4) {                                      \
                v0 += sm.part[w][t];     v1 += sm.part[w + 1][t];                  \
                v2 += sm.part[w + 2][t]; v3 += sm.part[w + 3][t];                  \
            }                                                                      \
            float v = (v0 + v1) + (v2 + v3);                                       \
            h = fmaf(h, Acoef, fmaf(v, inv_tau, pre));                             \
            float thv = fast_tanh(h);                                              \
            float tho = __shfl_xor_sync(0xffffffffu, thv, 1);                      \
            float ho  = __shfl_xor_sync(0xffffffffu, h,   1);                      \
            if (!(t & 1))                                                          \
                *(float2*)(outp + (size_t)(STEP) * H_DIM) = make_float2(h, ho);    \
            if (!(LAST)) {                                                         \
                unsigned long long pk = (t & 1) ? pack2(tho, thv)                  \
                                                : pack2(thv, tho);                 \
                uint32_t d = (uint32_t)(((P) ^ 1) * 2 * H_DIM * 4) + send_off;     \
                uint32_t m = msend_base + (((P) ^ 1) * 64u);                       \
                _Pragma("unroll")                                                  \
                for (int rr = 0; rr < 4; rr++)                                     \
                    st_async_b64(peer_th[peer0 + rr] + d, pk,                      \
                                 peer_th[peer0 + rr] + m);                         \
            }                                                                      \
            pre = fmaf(xn, inv_tau, c0);                                           \
        }                                                                          \
        (PH) ^= 1;                                                                 \
    }

    for (int s = 1; s < S_LEN - 1; s += 2) {
        STEP_BODY(s,     1, ph1, 0)
        STEP_BODY(s + 1, 0, ph0, 0)
    }
    STEP_BODY(S_LEN - 1, 1, ph1, 1)
#undef STEP_BODY

    cluster_sync();   // no CTA exits while peers' st.async may target its smem
}

extern "C" void kernel_launch(void* const* d_in, const int* in_sizes, int n_in,
                              void* d_out, int out_size)
{
    const float* x    = (const float*)d_in[0];
    const float* Wx   = (const float*)d_in[1];
    const float* Wh   = (const float*)d_in[2];
    const float* tau  = (const float*)d_in[3];
    const float* bias = (const float*)d_in[4];
    float* out = (float*)d_out;

    dim3 g1(H_DIM / BN, (B_SZ * S_LEN) / BM);
    xproj_kernel<<<g1, 256>>>(x, Wx, out);

    rec_kernel<<<NCLUSTERS * CRANKS, REC_THREADS>>>(Wh, tau, bias, out);
}

// round 11
// speedup vs baseline: 1.5393x; 1.0418x over previous
#include <cuda_runtime.h>
#include <cstdint>

#define S_LEN 2048
#define B_SZ  32
#define I_DIM 256
#define H_DIM 512

#define NCLUSTERS    16
#define CRANKS       8
#define ROWS_PER_CTA 64
#define REC_THREADS  512

// ---------------- PTX helpers ----------------
__device__ __forceinline__ uint32_t smem_u32(const void* p) {
    uint32_t a;
    asm("{ .reg .u64 t; cvta.to.shared.u64 t, %1; cvt.u32.u64 %0, t; }" : "=r"(a) : "l"(p));
    return a;
}
__device__ __forceinline__ uint32_t mapa_cluster(uint32_t addr, uint32_t rank) {
    uint32_t r;
    asm("mapa.shared::cluster.u32 %0, %1, %2;" : "=r"(r) : "r"(addr), "r"(rank));
    return r;
}
__device__ __forceinline__ void mbar_init(uint32_t mbar, uint32_t cnt) {
    asm volatile("mbarrier.init.shared.b64 [%0], %1;" :: "r"(mbar), "r"(cnt) : "memory");
}
__device__ __forceinline__ void mbar_expect_tx(uint32_t mbar, uint32_t bytes) {
    asm volatile("mbarrier.arrive.expect_tx.shared.b64 _, [%0], %1;" :: "r"(mbar), "r"(bytes) : "memory");
}
__device__ __forceinline__ void mbar_wait(uint32_t mbar, uint32_t phase) {
    uint32_t done = 0;
    while (!done) {
        asm volatile(
            "{\n\t.reg .pred p;\n\t"
            "mbarrier.try_wait.parity.acquire.cluster.shared::cta.b64 p, [%1], %2, 0x989680;\n\t"
            "selp.b32 %0, 1, 0, p;\n\t}"
            : "=r"(done) : "r"(mbar), "r"(phase) : "memory");
    }
}
__device__ __forceinline__ void st_async_b64(uint32_t daddr, unsigned long long v, uint32_t mbar) {
    asm volatile("st.async.shared::cluster.mbarrier::complete_tx::bytes.b64 [%0], %1, [%2];"
                 :: "r"(daddr), "l"(v), "r"(mbar) : "memory");
}
__device__ __forceinline__ unsigned long long ffma2(unsigned long long a, unsigned long long b,
                                                    unsigned long long c) {
    unsigned long long d;
    asm("fma.rn.f32x2 %0, %1, %2, %3;" : "=l"(d) : "l"(a), "l"(b), "l"(c));
    return d;
}
__device__ __forceinline__ float fold2(unsigned long long v) {
    union { unsigned long long u; float2 f; } c; c.u = v;
    return c.f.x + c.f.y;
}
__device__ __forceinline__ unsigned long long pack2(float x, float y) {
    unsigned long long r;
    asm("mov.b64 %0, {%1, %2};" : "=l"(r) : "r"(__float_as_uint(x)), "r"(__float_as_uint(y)));
    return r;
}
__device__ __forceinline__ float fast_tanh(float h) {
    float hc = fminf(fmaxf(h, -15.f), 15.f);
    float e2 = __expf(2.f * hc);
    return __fdividef(e2 - 1.f, e2 + 1.f);
}
__device__ __forceinline__ void cluster_sync() {
    asm volatile("barrier.cluster.arrive.aligned;\n\tbarrier.cluster.wait.aligned;" ::: "memory");
}

// ---------------- xproj GEMM (R3-proven): out[m,n] = sum_k x[m,k] * Wx[n,k] ----------------
#define BM 128
#define BN 128
#define BK 16

__global__ void __launch_bounds__(256, 2)
xproj_kernel(const float* __restrict__ x,
             const float* __restrict__ Wx,
             float* __restrict__ out)
{
    __shared__ float As[BK][BM];
    __shared__ float Bs[BK][BN];
    const int tid = threadIdx.x;
    const int m0 = blockIdx.y * BM;
    const int n0 = blockIdx.x * BN;
    const int tx = tid & 15;
    const int ty = tid >> 4;

    float acc[8][8];
#pragma unroll
    for (int i = 0; i < 8; i++)
#pragma unroll
        for (int j = 0; j < 8; j++) acc[i][j] = 0.f;

    const float* Aptr = x  + (size_t)m0 * I_DIM;
    const float* Bptr = Wx + (size_t)n0 * I_DIM;

    for (int k0 = 0; k0 < I_DIM; k0 += BK) {
#pragma unroll
        for (int l = 0; l < 2; l++) {
            int idx = tid + l * 256;
            int r   = idx >> 2;
            int c4  = (idx & 3) * 4;
            float4 a = *(const float4*)(Aptr + (size_t)r * I_DIM + k0 + c4);
            As[c4 + 0][r] = a.x; As[c4 + 1][r] = a.y;
            As[c4 + 2][r] = a.z; As[c4 + 3][r] = a.w;
            float4 b = *(const float4*)(Bptr + (size_t)r * I_DIM + k0 + c4);
            Bs[c4 + 0][r] = b.x; Bs[c4 + 1][r] = b.y;
            Bs[c4 + 2][r] = b.z; Bs[c4 + 3][r] = b.w;
        }
        __syncthreads();
#pragma unroll
        for (int kk = 0; kk < BK; kk++) {
            float ra[8], rb[8];
            float4 ra0 = *(const float4*)&As[kk][ty * 8];
            float4 ra1 = *(const float4*)&As[kk][ty * 8 + 4];
            ra[0]=ra0.x; ra[1]=ra0.y; ra[2]=ra0.z; ra[3]=ra0.w;
            ra[4]=ra1.x; ra[5]=ra1.y; ra[6]=ra1.z; ra[7]=ra1.w;
            float4 rb0 = *(const float4*)&Bs[kk][tx * 8];
            float4 rb1 = *(const float4*)&Bs[kk][tx * 8 + 4];
            rb[0]=rb0.x; rb[1]=rb0.y; rb[2]=rb0.z; rb[3]=rb0.w;
            rb[4]=rb1.x; rb[5]=rb1.y; rb[6]=rb1.z; rb[7]=rb1.w;
#pragma unroll
            for (int i = 0; i < 8; i++)
#pragma unroll
                for (int j = 0; j < 8; j++)
                    acc[i][j] += ra[i] * rb[j];
        }
        __syncthreads();
    }

#pragma unroll
    for (int i = 0; i < 8; i++) {
        float* o = out + (size_t)(m0 + ty * 8 + i) * H_DIM + n0 + tx * 8;
        *(float4*)o       = make_float4(acc[i][0], acc[i][1], acc[i][2], acc[i][3]);
        *(float4*)(o + 4) = make_float4(acc[i][4], acc[i][5], acc[i][6], acc[i][7]);
    }
}

// ---------------- recurrence (staggered batches, R7 data path) ----------------
// 16 clusters x 8 CTAs; cluster c: batches (2c, 2c+1). CTA rank r: rows
// [r*64, r*64+64), Wh in registers (f32x2; shared by both batches).
// Per step: two phases. Phase bb: mbar[P][bb] wait -> broadcast-LDS FFMA2
// GEMV (32 FFMA2 + 8 LDS.128/thread) -> float2 partials (parity-double-
// buffered) -> named bar bb+1 (bar.arrive for non-tail warps = non-blocking)
// -> 64-thread tail (warps 0-1 for b0 / 2-3 for b1): coalesced reduce, 2-FMA
// update, tanh, pair shfl, 4x st.async b64 into peers' th[P^1][bb].
// Batch-bb messages transit while the OTHER batch's phase computes -> hidden.
struct RecSmem {
    float th[2][2][H_DIM];        // [parity][batch][k]      8KB (st.async dest)
    float part[2][2][16][64];     // [parity][batch][w][row] 16KB
    unsigned long long mbar[2][2];// [parity][batch]
};

__global__ void __cluster_dims__(CRANKS, 1, 1) __launch_bounds__(REC_THREADS, 1)
rec_kernel(const float* __restrict__ Wh,
           const float* __restrict__ tau,
           const float* __restrict__ bias,
           float* __restrict__ out)
{
    __shared__ __align__(16) RecSmem sm;

    const int cid  = blockIdx.x / CRANKS;
    const int rank = blockIdx.x % CRANKS;
    const int t    = threadIdx.x;
    const int jp   = t & 31;
    const int kb   = t >> 5;
    const int j0   = 2 * jp;

    // Wh slice in registers (rows j0, j0+1; k in [kb*32, kb*32+32))
    unsigned long long wp0[16], wp1[16];
    {
        const ulonglong2* r0 = (const ulonglong2*)(Wh + (size_t)(rank * ROWS_PER_CTA + j0)     * H_DIM + kb * 32);
        const ulonglong2* r1 = (const ulonglong2*)(Wh + (size_t)(rank * ROWS_PER_CTA + j0 + 1) * H_DIM + kb * 32);
#pragma unroll
        for (int i = 0; i < 8; i++) {
            ulonglong2 a = r0[i]; wp0[2*i] = a.x; wp0[2*i+1] = a.y;
            ulonglong2 b = r1[i]; wp1[2*i] = b.x; wp1[2*i+1] = b.y;
        }
    }

    const uint32_t th_base   = smem_u32(&sm.th[0][0][0]);
    const uint32_t mbar_base = smem_u32(&sm.mbar[0][0]);
    const uint32_t mbar_rel  = mbar_base - th_base;

    uint32_t peer_th[CRANKS];
#pragma unroll
    for (int r = 0; r < CRANKS; r++) peer_th[r] = mapa_cluster(th_base, r);

    // 4 mbars [p][b] at offset (p*2+b)*8, each expecting 2048B (8 src x 32 b64)
    if (t < 4) {
        mbar_init(mbar_base + t * 8, 1);
        mbar_expect_tx(mbar_base + t * 8, 2048);
    }
    __syncthreads();
    cluster_sync();   // peers' mbars live before any st.async

    // tail/owner state: t<64 -> batch grp 0 (rows rank*64+t), 64<=t<128 -> grp 1
    const int tl  = t & 63;
    const int grp = (t >> 6) & 1;
    const bool owner = (t < 128);
    const int hg = rank * ROWS_PER_CTA + tl;
    float* outp = out + (size_t)(cid * 2 + grp) * S_LEN * H_DIM + hg;

    float h = 0.f, inv_tau = 1.f, Acoef = 0.f, c0 = 0.f, pre = 0.f;
    if (owner) {
        inv_tau = 1.0f / tau[hg];
        Acoef   = 1.0f - inv_tau;
        c0      = bias[hg] * inv_tau;
    }
    const uint32_t send_off = (uint32_t)(hg & ~1) * 4u;   // within a th image
    const int peer0 = (t & 1) * 4;    // even row: peers 0-3, odd: peers 4-7

    // ---- step 0: v = 0, h = xp/tau + bias/tau; send th into parity-1 ----
    if (owner) {
        float xp = outp[0];
        pre = fmaf(xp, inv_tau, c0);
        h = pre;
        float thv = fast_tanh(h);
        float tho = __shfl_xor_sync(0xffffffffu, thv, 1);
        float ho  = __shfl_xor_sync(0xffffffffu, h,   1);
        if (!(t & 1)) *(float2*)outp = make_float2(h, ho);
        unsigned long long pk = (t & 1) ? pack2(tho, thv) : pack2(thv, tho);
        uint32_t d = (uint32_t)((2 + grp) * 2048) + send_off;   // th[1][grp]
        uint32_t m = mbar_rel + (uint32_t)(2 + grp) * 8u;       // mbar[1][grp]
#pragma unroll
        for (int rr = 0; rr < 4; rr++)
            st_async_b64(peer_th[peer0 + rr] + d, pk, peer_th[peer0 + rr] + m);
        float xn = outp[(size_t)1 * H_DIM];
        pre = fmaf(xn, inv_tau, c0);
    }

    uint32_t ph00 = 0, ph01 = 0, ph10 = 0, ph11 = 0;

    // one batch phase: wait -> GEMV -> partials -> bar -> tail
#define PHASE_BODY(STEP, P, BB, PH, BARID, LAST)                                   \
    {                                                                              \
        mbar_wait(mbar_base + ((P) * 2 + (BB)) * 8, (PH));                         \
        if (t == 0) mbar_expect_tx(mbar_base + ((P) * 2 + (BB)) * 8, 2048);        \
        const ulonglong2* tc = (const ulonglong2*)&sm.th[(P)][(BB)][kb * 32];      \
        unsigned long long a0e = 0ull, a0o = 0ull, a1e = 0ull, a1o = 0ull;         \
        _Pragma("unroll")                                                          \
        for (int i = 0; i < 8; i++) {                                              \
            ulonglong2 U = tc[i];                                                  \
            a0e = ffma2(wp0[2*i],   U.x, a0e);                                     \
            a0o = ffma2(wp0[2*i+1], U.y, a0o);                                     \
            a1e = ffma2(wp1[2*i],   U.x, a1e);                                     \
            a1o = ffma2(wp1[2*i+1], U.y, a1o);                                     \
        }                                                                          \
        *(float2*)&sm.part[(P)][(BB)][kb][j0] =                                    \
            make_float2(fold2(a0e) + fold2(a0o), fold2(a1e) + fold2(a1o));         \
        if (owner && grp == (BB)) {                                                \
            asm volatile("bar.sync " #BARID ", 512;" ::: "memory");                \
            float v0 = sm.part[(P)][(BB)][0][tl], v1 = sm.part[(P)][(BB)][1][tl];  \
            float v2 = sm.part[(P)][(BB)][2][tl], v3 = sm.part[(P)][(BB)][3][tl];  \
            _Pragma("unroll")                                                      \
            for (int w = 4; w < 16; w += 4) {                                      \
                v0 += sm.part[(P)][(BB)][w][tl];                                   \
                v1 += sm.part[(P)][(BB)][w + 1][tl];                               \
                v2 += sm.part[(P)][(BB)][w + 2][tl];                               \
                v3 += sm.part[(P)][(BB)][w + 3][tl];                               \
            }                                                                      \
            float v = (v0 + v1) + (v2 + v3);                                       \
            h = fmaf(h, Acoef, fmaf(v, inv_tau, pre));                             \
            float thv = fast_tanh(h);                                              \
            float tho = __shfl_xor_sync(0xffffffffu, thv, 1);                      \
            float ho  = __shfl_xor_sync(0xffffffffu, h,   1);                      \
            if (!(t & 1))                                                          \
                *(float2*)(outp + (size_t)(STEP) * H_DIM) = make_float2(h, ho);    \
            if (!(LAST)) {                                                         \
                unsigned long long pk = (t & 1) ? pack2(tho, thv)                  \
                                                : pack2(thv, tho);                 \
                uint32_t d = (uint32_t)((((P) ^ 1) * 2 + (BB)) * 2048) + send_off; \
                uint32_t m = mbar_rel + (uint32_t)((((P) ^ 1) * 2 + (BB))) * 8u;   \
                _Pragma("unroll")                                                  \
                for (int rr = 0; rr < 4; rr++)                                     \
                    st_async_b64(peer_th[peer0 + rr] + d, pk,                      \
                                 peer_th[peer0 + rr] + m);                         \
            }                                                                      \
            pre = fmaf(xn_, inv_tau, c0);                                          \
        } else {                                                                   \
            asm volatile("bar.arrive " #BARID ", 512;" ::: "memory");              \
        }                                                                          \
        (PH) ^= 1;                                                                 \
    }

#define STEP_BODY(STEP, P, PHB0, PHB1, LAST)                                       \
    {                                                                              \
        float xn_ = 0.f;                                                           \
        if (owner && !(LAST)) xn_ = outp[(size_t)((STEP) + 1) * H_DIM];            \
        PHASE_BODY(STEP, P, 0, PHB0, 1, LAST)                                      \
        PHASE_BODY(STEP, P, 1, PHB1, 2, LAST)                                      \
    }

    for (int s = 1; s < S_LEN - 1; s += 2) {
        STEP_BODY(s,     1, ph10, ph11, 0)
        STEP_BODY(s + 1, 0, ph00, ph01, 0)
    }
    STEP_BODY(S_LEN - 1, 1, ph10, ph11, 1)
#undef STEP_BODY
#undef PHASE_BODY

    cluster_sync();   // no CTA exits while peers' st.async may target its smem
}

extern "C" void kernel_launch(void* const* d_in, const int* in_sizes, int n_in,
                              void* d_out, int out_size)
{
    const float* x    = (const float*)d_in[0];
    const float* Wx   = (const float*)d_in[1];
    const float* Wh   = (const float*)d_in[2];
    const float* tau  = (const float*)d_in[3];
    const float* bias = (const float*)d_in[4];
    float* out = (float*)d_out;

    dim3 g1(H_DIM / BN, (B_SZ * S_LEN) / BM);
    xproj_kernel<<<g1, 256>>>(x, Wx, out);

    rec_kernel<<<NCLUSTERS * CRANKS, REC_THREADS>>>(Wh, tau, bias, out);
}